// round 3
// baseline (speedup 1.0000x reference)
#include <cuda_runtime.h>

// UnarySqrt recurrence, unipolar, jk_trace=True.
// On exact {0.0f, 1.0f} IEEE bit patterns (0x00000000 / 0x3F800000) the
// recurrence is pure bitwise logic:
//   out   = trace | x        ( == (1-trace)*x + trace, disjoint add )
//   trace'= x & ~trace       ( == out * (1-trace) )
// Verified: both operands only ever hold 0x0 or 0x3F800000, so OR/ANDN
// reproduce the float math bit-exactly.
//
// T=64 sequential steps, N=1,048,576 channels. Pure HBM streaming (512MB).
// R3: 2 independent uint4 streams/thread, 128-thread CTAs x 1024 blocks
// (finer CTA granularity -> higher resident warps + less cross-CTA spread).

#define T_STEPS 64

__device__ __forceinline__ uint4 ldcs4(const uint4* p) { return __ldcs(p); }

__global__ __launch_bounds__(128)
void unary_sqrt_kernel(const uint4* __restrict__ bits,
                       const uint4* __restrict__ trace0,
                       uint4* __restrict__ out,
                       int nvec, int half)
{
    int i = blockIdx.x * blockDim.x + threadIdx.x;
    if (i >= half) return;
    int j = i + half;

    uint4 ta = __ldcs(&trace0[i]);
    uint4 tb = __ldcs(&trace0[j]);

    #pragma unroll 8
    for (int t = 0; t < T_STEPS; ++t) {
        const size_t base = (size_t)t * nvec;
        uint4 xa = __ldcs(&bits[base + i]);
        uint4 xb = __ldcs(&bits[base + j]);

        uint4 oa, ob;
        oa.x = xa.x | ta.x;  oa.y = xa.y | ta.y;
        oa.z = xa.z | ta.z;  oa.w = xa.w | ta.w;
        ob.x = xb.x | tb.x;  ob.y = xb.y | tb.y;
        ob.z = xb.z | tb.z;  ob.w = xb.w | tb.w;

        ta.x = xa.x & ~ta.x;  ta.y = xa.y & ~ta.y;
        ta.z = xa.z & ~ta.z;  ta.w = xa.w & ~ta.w;
        tb.x = xb.x & ~tb.x;  tb.y = xb.y & ~tb.y;
        tb.z = xb.z & ~tb.z;  tb.w = xb.w & ~tb.w;

        __stcs(&out[base + i], oa);
        __stcs(&out[base + j], ob);
    }
}

extern "C" void kernel_launch(void* const* d_in, const int* in_sizes, int n_in,
                              void* d_out, int out_size)
{
    // metadata order: input [T, N] float32, trace0 [N] float32
    const uint4* bits   = (const uint4*)d_in[0];
    const uint4* trace0 = (const uint4*)d_in[1];
    uint4*       out    = (uint4*)d_out;

    int N    = in_sizes[1];   // 1048576
    int nvec = N / 4;         // 262144 uint4 vectors
    int half = nvec / 2;      // 131072

    int threads = 128;
    int blocks  = (half + threads - 1) / threads;  // 1024
    unary_sqrt_kernel<<<blocks, threads>>>(bits, trace0, out, nvec, half);
}